// round 8
// baseline (speedup 1.0000x reference)
#include <cuda_runtime.h>
#include <cstdint>

#define N_NODES 100000
#define N_EDGES 640000
#define N_FEAT 128
#define N_CLASSES 16
#define NB_NODES 391               // ceil(N_NODES/256)

// Scratch (no allocations allowed). g_cnt is zero at program load and
// re-zeroed by zero_kernel at the end of every call (invariant).
__device__ float4 g_y[N_NODES * 4];        // x @ W_l^T   (16 floats/node)
__device__ float4 g_z[N_NODES * 4];        // x @ W_r^T + b_l
__device__ int    g_cnt[N_NODES];          // histogram -> cursor -> end
__device__ int    g_start[N_NODES];        // CSR start offsets
__device__ int    g_csr_src[N_EDGES];      // src id per CSR slot

// Packed fp32x2 FMA (sm_103a native; ptxas never auto-fuses this)
#define FMA_F32X2(d, a, b, c) \
    asm("fma.rn.f32x2 %0, %1, %2, %3;" : "=l"(d) : "l"(a), "l"(b), "l"(c))

__device__ __forceinline__ unsigned long long pack2(float lo, float hi) {
    unsigned long long r;
    asm("mov.b64 %0, {%1, %2};" : "=l"(r) : "f"(lo), "f"(hi));
    return r;
}
__device__ __forceinline__ float sum2(unsigned long long v) {
    float lo, hi;
    asm("mov.b64 {%0, %1}, %2;" : "=f"(lo), "=f"(hi) : "l"(v));
    return lo + hi;
}

// Block-local dtype detect: 64 threads each test one 8B word of edge_index.
// int32 truth -> some word >= 2^32 w.p. ~1-1e-5 each; 64 words => certain.
// Result shared via smem flag. Call with a __shared__ int* and tid.
__device__ __forceinline__ int detect_is64_block(const void* ei, int tid,
                                                 int* s_flag) {
    if (tid == 0) *s_flag = 0;
    __syncthreads();
    if (tid < 64) {
        unsigned long long w = __ldg(&((const unsigned long long*)ei)[tid]);
        if (w >= (1ULL << 32)) *s_flag = 1;     // benign same-value race
    }
    __syncthreads();
    return !(*s_flag);
}

__device__ __forceinline__ int load_dst(const void* ei, int e, int is64) {
    if (is64) return (int)__ldg(&((const long long*)ei)[N_EDGES + e]);
    return __ldg(&((const int*)ei)[N_EDGES + e]);
}
__device__ __forceinline__ int load_src(const void* ei, int e, int is64) {
    if (is64) return (int)__ldg(&((const long long*)ei)[e]);
    return __ldg(&((const int*)ei)[e]);
}

// ---------------------------------------------------------------------------
// Projection + fused in-degree histogram.
// Block of 256 threads: 256 nodes (coalesced smem staging of x, pad-9 float4
// rows, weights smem-resident, packed f32x2 FMAs) + histograms a disjoint
// ~1637-edge slice (atomic traffic drains under the FMA-bound loop).
// Requires g_cnt == 0 at entry (invariant).
// ---------------------------------------------------------------------------
#define CHUNK_F4 8
#define TILE_STRIDE 9
#define EDGES_PER_BLOCK ((N_EDGES + NB_NODES - 1) / NB_NODES)   // 1637

__global__ __launch_bounds__(256) void proj_kernel(
    const float* __restrict__ x,
    const float* __restrict__ Wl,
    const float* __restrict__ bl,
    const float* __restrict__ Wr,
    const void* __restrict__ ei)
{
    __shared__ float4 sWl[N_CLASSES * (N_FEAT / 4)];   // 8 KB
    __shared__ float4 sWr[N_CLASSES * (N_FEAT / 4)];   // 8 KB
    __shared__ float  sb[N_CLASSES];
    __shared__ float4 tile[256 * TILE_STRIDE];         // 36 KB
    __shared__ int    s_flag;

    int tid = threadIdx.x;
    int is64 = detect_is64_block(ei, tid, &s_flag);

    const float4* Wl4 = (const float4*)Wl;
    const float4* Wr4 = (const float4*)Wr;
    for (int i = tid; i < N_CLASSES * (N_FEAT / 4); i += 256) {
        sWl[i] = Wl4[i];
        sWr[i] = Wr4[i];
    }
    if (tid < N_CLASSES) sb[tid] = bl[tid];

    // Fused histogram slice (independent of the FMA work below).
    {
        int e0 = blockIdx.x * EDGES_PER_BLOCK;
        int e1 = min(e0 + EDGES_PER_BLOCK, N_EDGES);
        for (int e = e0 + tid; e < e1; e += 256) {
            atomicAdd(&g_cnt[load_dst(ei, e, is64)], 1);
        }
    }

    int base = blockIdx.x * 256;
    int node = base + tid;
    bool active = (node < N_NODES);

    unsigned long long accl[N_CLASSES];
    unsigned long long accr[N_CLASSES];
#pragma unroll
    for (int c = 0; c < N_CLASSES; c++) { accl[c] = 0ULL; accr[c] = 0ULL; }

    const float4* x4 = (const float4*)x;

    for (int ch = 0; ch < N_FEAT / (4 * CHUNK_F4); ch++) {
        __syncthreads();
#pragma unroll
        for (int i = 0; i < CHUNK_F4; i++) {
            int f = tid + i * 256;
            int n = f >> 3;
            int j = f & 7;
            int gn = base + n;
            if (gn >= N_NODES) gn = N_NODES - 1;
            tile[n * TILE_STRIDE + j] =
                x4[(size_t)gn * (N_FEAT / 4) + ch * CHUNK_F4 + j];
        }
        __syncthreads();

#pragma unroll
        for (int j = 0; j < CHUNK_F4; j++) {
            float4 xv = tile[tid * TILE_STRIDE + j];
            unsigned long long xlo = pack2(xv.x, xv.y);
            unsigned long long xhi = pack2(xv.z, xv.w);
            int k = ch * CHUNK_F4 + j;
#pragma unroll
            for (int c = 0; c < N_CLASSES; c++) {
                float4 wl = sWl[c * (N_FEAT / 4) + k];
                FMA_F32X2(accl[c], xlo, pack2(wl.x, wl.y), accl[c]);
                FMA_F32X2(accl[c], xhi, pack2(wl.z, wl.w), accl[c]);
                float4 wr = sWr[c * (N_FEAT / 4) + k];
                FMA_F32X2(accr[c], xlo, pack2(wr.x, wr.y), accr[c]);
                FMA_F32X2(accr[c], xhi, pack2(wr.z, wr.w), accr[c]);
            }
        }
    }

    if (active) {
#pragma unroll
        for (int c4 = 0; c4 < 4; c4++) {
            float4 vy, vz;
            vy.x = sum2(accl[c4 * 4 + 0]);
            vy.y = sum2(accl[c4 * 4 + 1]);
            vy.z = sum2(accl[c4 * 4 + 2]);
            vy.w = sum2(accl[c4 * 4 + 3]);
            vz.x = sum2(accr[c4 * 4 + 0]) + sb[c4 * 4 + 0];
            vz.y = sum2(accr[c4 * 4 + 1]) + sb[c4 * 4 + 1];
            vz.z = sum2(accr[c4 * 4 + 2]) + sb[c4 * 4 + 2];
            vz.w = sum2(accr[c4 * 4 + 3]) + sb[c4 * 4 + 3];
            g_y[node * 4 + c4] = vy;
            g_z[node * 4 + c4] = vz;
        }
    }
}

// ---------------------------------------------------------------------------
// Full exclusive scan in ONE single-block kernel (replaces 3 kernels).
// 1024 threads; thread t owns chunk [t*98, t*98+98): local sum -> block
// Hillis-Steele scan -> chunk writeback producing g_start + cursor (g_cnt).
// ---------------------------------------------------------------------------
#define SCAN_CHUNK ((N_NODES + 1023) / 1024)      // 98

__global__ __launch_bounds__(1024) void scan_kernel() {
    __shared__ int s[1024];
    int tid = threadIdx.x;
    int lo = tid * SCAN_CHUNK;
    int hi = min(lo + SCAN_CHUNK, N_NODES);

    int sum = 0;
    for (int i = lo; i < hi; i++) sum += g_cnt[i];
    s[tid] = sum;
    __syncthreads();

#pragma unroll
    for (int off = 1; off < 1024; off <<= 1) {
        int t = (tid >= off) ? s[tid - off] : 0;
        __syncthreads();
        s[tid] += t;
        __syncthreads();
    }

    int run = s[tid] - sum;                        // exclusive offset
    for (int i = lo; i < hi; i++) {
        int c = g_cnt[i];
        g_start[i] = run;
        g_cnt[i]   = run;                          // scatter cursor
        run += c;
    }
}

// ---------------------------------------------------------------------------
// Scatter src ids into per-dst CSR slots (2 edges/thread).
// After this, g_cnt[i] == end offset of node i's list.
// ---------------------------------------------------------------------------
__global__ __launch_bounds__(256) void scatter_kernel(const void* __restrict__ ei) {
    __shared__ int s_flag;
    int tid = threadIdx.x;
    int is64 = detect_is64_block(ei, tid, &s_flag);

    int e = (blockIdx.x * 256 + tid) * 2;
    if (e >= N_EDGES) return;
#pragma unroll
    for (int u = 0; u < 2; u++) {
        int ee = e + u;
        if (ee >= N_EDGES) break;
        int src = load_src(ei, ee, is64);
        int dst = load_dst(ei, ee, is64);
        int pos = atomicAdd(&g_cnt[dst], 1);
        g_csr_src[pos] = src;
    }
}

// ---------------------------------------------------------------------------
// Gather + finalize (fused): 4 threads per node, one float4 quad each.
// Index load is a 4-lane broadcast; the 4 quads of g_y[src] are one
// contiguous 64B segment per edge. Register accumulation (zero float
// atomics), then out = relu(acc/max(deg,1) + z), deg = end - start.
// ---------------------------------------------------------------------------
__global__ __launch_bounds__(256) void gather_fin_kernel(float* __restrict__ out) {
    int t = blockIdx.x * 256 + threadIdx.x;
    if (t >= N_NODES * 4) return;
    int node = t >> 2;
    int q = t & 3;

    int s = g_start[node];
    int e = g_cnt[node];

    float4 a = make_float4(0.f, 0.f, 0.f, 0.f);
    for (int i = s; i < e; i++) {
        int src = __ldg(&g_csr_src[i]);
        float4 v = g_y[src * 4 + q];
        a.x += v.x; a.y += v.y; a.z += v.z; a.w += v.w;
    }

    float inv = __fdividef(1.0f, fmaxf((float)(e - s), 1.0f));
    float4 z = g_z[node * 4 + q];
    float4 o;
    o.x = fmaxf(fmaf(a.x, inv, z.x), 0.0f);
    o.y = fmaxf(fmaf(a.y, inv, z.y), 0.0f);
    o.z = fmaxf(fmaf(a.z, inv, z.z), 0.0f);
    o.w = fmaxf(fmaf(a.w, inv, z.w), 0.0f);
    ((float4*)out)[t] = o;
}

// ---------------------------------------------------------------------------
// Re-establish the invariant for the next call: g_cnt = 0.
// ---------------------------------------------------------------------------
__global__ __launch_bounds__(256) void zero_kernel() {
    int i = blockIdx.x * 256 + threadIdx.x;
    if (i < N_NODES) g_cnt[i] = 0;
}

extern "C" void kernel_launch(void* const* d_in, const int* in_sizes, int n_in,
                              void* d_out, int out_size) {
    const float* x  = (const float*)d_in[0];
    const void*  ei = d_in[1];
    const float* Wl = (const float*)d_in[2];
    const float* bl = (const float*)d_in[3];
    const float* Wr = (const float*)d_in[4];
    float* out = (float*)d_out;

    proj_kernel<<<NB_NODES, 256>>>(x, Wl, bl, Wr, ei);
    scan_kernel<<<1, 1024>>>();
    scatter_kernel<<<(N_EDGES / 2 + 255) / 256, 256>>>(ei);
    gather_fin_kernel<<<(N_NODES * 4 + 255) / 256, 256>>>(out);
    zero_kernel<<<NB_NODES, 256>>>();
}

// round 11
// speedup vs baseline: 2.8685x; 2.8685x over previous
#include <cuda_runtime.h>
#include <cstdint>

#define N_NODES 100000
#define N_EDGES 640000
#define N_FEAT 128
#define N_CLASSES 16
#define NB_NODES 391               // ceil(N_NODES/256)

// Scratch (no allocations allowed). Invariants at kernel_launch entry:
// g_cnt == 0 (restored by gather_fin), g_scan_ctr == 0 (restored by
// gather_fin). Both hold at load time (zero-init) and after every call.
__device__ float4 g_y[N_NODES * 4];        // x @ W_l^T   (16 floats/node)
__device__ float4 g_z[N_NODES * 4];        // x @ W_r^T + b_l
__device__ int    g_cnt[N_NODES];          // histogram -> scatter cursor
__device__ int    g_start[N_NODES];        // CSR start offsets (excl. scan)
__device__ int    g_blocksum[NB_NODES];    // per-block degree sums
__device__ int    g_scan_ctr;              // publish counter for scan
__device__ int    g_csr_src[N_EDGES];      // src id per CSR slot

// Packed fp32x2 FMA (sm_103a native; ptxas never auto-fuses this)
#define FMA_F32X2(d, a, b, c) \
    asm("fma.rn.f32x2 %0, %1, %2, %3;" : "=l"(d) : "l"(a), "l"(b), "l"(c))

__device__ __forceinline__ unsigned long long pack2(float lo, float hi) {
    unsigned long long r;
    asm("mov.b64 %0, {%1, %2};" : "=l"(r) : "f"(lo), "f"(hi));
    return r;
}
__device__ __forceinline__ float sum2(unsigned long long v) {
    float lo, hi;
    asm("mov.b64 {%0, %1}, %2;" : "=f"(lo), "=f"(hi) : "l"(v));
    return lo + hi;
}

// Block-local dtype detect: 64 threads each test one 8B word of edge_index.
// int32 truth -> word >= 2^32 w.p. ~1-1e-5 each; 64 words => certain.
__device__ __forceinline__ int detect_is64_block(const void* ei, int tid,
                                                 int* s_flag) {
    if (tid == 0) *s_flag = 0;
    __syncthreads();
    if (tid < 64) {
        unsigned long long w = __ldg(&((const unsigned long long*)ei)[tid]);
        if (w >= (1ULL << 32)) *s_flag = 1;     // benign same-value race
    }
    __syncthreads();
    return !(*s_flag);
}

__device__ __forceinline__ int load_dst(const void* ei, int e, int is64) {
    if (is64) return (int)__ldg(&((const long long*)ei)[N_EDGES + e]);
    return __ldg(&((const int*)ei)[N_EDGES + e]);
}
__device__ __forceinline__ int load_src(const void* ei, int e, int is64) {
    if (is64) return (int)__ldg(&((const long long*)ei)[e]);
    return __ldg(&((const int*)ei)[e]);
}

// ---------------------------------------------------------------------------
// Projection + fused in-degree histogram (g_cnt must be 0 at entry).
// ---------------------------------------------------------------------------
#define CHUNK_F4 8
#define TILE_STRIDE 9
#define EDGES_PER_BLOCK ((N_EDGES + NB_NODES - 1) / NB_NODES)   // 1637

__global__ __launch_bounds__(256) void proj_kernel(
    const float* __restrict__ x,
    const float* __restrict__ Wl,
    const float* __restrict__ bl,
    const float* __restrict__ Wr,
    const void* __restrict__ ei)
{
    __shared__ float4 sWl[N_CLASSES * (N_FEAT / 4)];   // 8 KB
    __shared__ float4 sWr[N_CLASSES * (N_FEAT / 4)];   // 8 KB
    __shared__ float  sb[N_CLASSES];
    __shared__ float4 tile[256 * TILE_STRIDE];         // 36 KB
    __shared__ int    s_flag;

    int tid = threadIdx.x;
    int is64 = detect_is64_block(ei, tid, &s_flag);

    const float4* Wl4 = (const float4*)Wl;
    const float4* Wr4 = (const float4*)Wr;
    for (int i = tid; i < N_CLASSES * (N_FEAT / 4); i += 256) {
        sWl[i] = Wl4[i];
        sWr[i] = Wr4[i];
    }
    if (tid < N_CLASSES) sb[tid] = bl[tid];

    // Fused histogram slice (drains under the FMA-bound loop below).
    {
        int e0 = blockIdx.x * EDGES_PER_BLOCK;
        int e1 = min(e0 + EDGES_PER_BLOCK, N_EDGES);
        for (int e = e0 + tid; e < e1; e += 256) {
            atomicAdd(&g_cnt[load_dst(ei, e, is64)], 1);
        }
    }

    int base = blockIdx.x * 256;
    int node = base + tid;
    bool active = (node < N_NODES);

    unsigned long long accl[N_CLASSES];
    unsigned long long accr[N_CLASSES];
#pragma unroll
    for (int c = 0; c < N_CLASSES; c++) { accl[c] = 0ULL; accr[c] = 0ULL; }

    const float4* x4 = (const float4*)x;

    for (int ch = 0; ch < N_FEAT / (4 * CHUNK_F4); ch++) {
        __syncthreads();
#pragma unroll
        for (int i = 0; i < CHUNK_F4; i++) {
            int f = tid + i * 256;
            int n = f >> 3;
            int j = f & 7;
            int gn = base + n;
            if (gn >= N_NODES) gn = N_NODES - 1;
            tile[n * TILE_STRIDE + j] =
                x4[(size_t)gn * (N_FEAT / 4) + ch * CHUNK_F4 + j];
        }
        __syncthreads();

#pragma unroll
        for (int j = 0; j < CHUNK_F4; j++) {
            float4 xv = tile[tid * TILE_STRIDE + j];
            unsigned long long xlo = pack2(xv.x, xv.y);
            unsigned long long xhi = pack2(xv.z, xv.w);
            int k = ch * CHUNK_F4 + j;
#pragma unroll
            for (int c = 0; c < N_CLASSES; c++) {
                float4 wl = sWl[c * (N_FEAT / 4) + k];
                FMA_F32X2(accl[c], xlo, pack2(wl.x, wl.y), accl[c]);
                FMA_F32X2(accl[c], xhi, pack2(wl.z, wl.w), accl[c]);
                float4 wr = sWr[c * (N_FEAT / 4) + k];
                FMA_F32X2(accr[c], xlo, pack2(wr.x, wr.y), accr[c]);
                FMA_F32X2(accr[c], xhi, pack2(wr.z, wr.w), accr[c]);
            }
        }
    }

    if (active) {
#pragma unroll
        for (int c4 = 0; c4 < 4; c4++) {
            float4 vy, vz;
            vy.x = sum2(accl[c4 * 4 + 0]);
            vy.y = sum2(accl[c4 * 4 + 1]);
            vy.z = sum2(accl[c4 * 4 + 2]);
            vy.w = sum2(accl[c4 * 4 + 3]);
            vz.x = sum2(accr[c4 * 4 + 0]) + sb[c4 * 4 + 0];
            vz.y = sum2(accr[c4 * 4 + 1]) + sb[c4 * 4 + 1];
            vz.z = sum2(accr[c4 * 4 + 2]) + sb[c4 * 4 + 2];
            vz.w = sum2(accr[c4 * 4 + 3]) + sb[c4 * 4 + 3];
            g_y[node * 4 + c4] = vy;
            g_z[node * 4 + c4] = vz;
        }
    }
}

// ---------------------------------------------------------------------------
// Single-kernel exclusive scan (391 blocks, all resident in wave 1 -> the
// publish-and-wait grid barrier cannot deadlock).
// Phase 1: per-block Hillis-Steele scan of its 256 degree counts.
// Phase 2: publish block sum, __threadfence, counter++; spin until all 391
//          published (~1-2us); strided-reduce the sums with index < bid to
//          get this block's offset; write g_start + scatter cursor.
// ---------------------------------------------------------------------------
__global__ __launch_bounds__(256) void scan_kernel() {
    __shared__ int s[256];
    __shared__ int red[256];
    int tid = threadIdx.x;
    int bid = blockIdx.x;
    int i = bid * 256 + tid;
    int v = (i < N_NODES) ? g_cnt[i] : 0;
    s[tid] = v;
    __syncthreads();
#pragma unroll
    for (int off = 1; off < 256; off <<= 1) {
        int t = (tid >= off) ? s[tid - off] : 0;
        __syncthreads();
        s[tid] += t;
        __syncthreads();
    }
    int local_excl = s[tid] - v;

    if (tid == 255) {
        g_blocksum[bid] = s[255];
        __threadfence();
        atomicAdd(&g_scan_ctr, 1);
    }

    // Grid barrier: wait for all blocks' sums.
    if (tid == 0) {
        while (*((volatile int*)&g_scan_ctr) < NB_NODES) { }
    }
    __syncthreads();

    // This block's offset = sum of g_blocksum[p] for p < bid.
    int part = 0;
    for (int p = tid; p < bid; p += 256) part += g_blocksum[p];
    red[tid] = part;
    __syncthreads();
#pragma unroll
    for (int off = 128; off > 0; off >>= 1) {
        if (tid < off) red[tid] += red[tid + off];
        __syncthreads();
    }
    int boff = red[0];

    if (i < N_NODES) {
        int st = local_excl + boff;
        g_start[i] = st;
        g_cnt[i] = st;                              // scatter cursor
    }
}

// ---------------------------------------------------------------------------
// Scatter src ids into per-dst CSR slots (2 edges/thread).
// ---------------------------------------------------------------------------
__global__ __launch_bounds__(256) void scatter_kernel(const void* __restrict__ ei) {
    __shared__ int s_flag;
    int tid = threadIdx.x;
    int is64 = detect_is64_block(ei, tid, &s_flag);

    int e = (blockIdx.x * 256 + tid) * 2;
    if (e >= N_EDGES) return;
#pragma unroll
    for (int u = 0; u < 2; u++) {
        int ee = e + u;
        if (ee >= N_EDGES) break;
        int src = load_src(ei, ee, is64);
        int dst = load_dst(ei, ee, is64);
        int pos = atomicAdd(&g_cnt[dst], 1);
        g_csr_src[pos] = src;
    }
}

// ---------------------------------------------------------------------------
// Gather + finalize (fused): 4 threads per node, one float4 quad each.
// Software-pipelined index prefetch + dual accumulators. end[i] ==
// g_start[i+1]; g_cnt is not read here, so lane q==0 re-zeroes it and
// thread 0 re-zeroes g_scan_ctr (restores invariants for the next call).
// ---------------------------------------------------------------------------
__global__ __launch_bounds__(256) void gather_fin_kernel(float* __restrict__ out) {
    int t = blockIdx.x * 256 + threadIdx.x;
    if (t == 0) g_scan_ctr = 0;                    // restore invariant
    if (t >= N_NODES * 4) return;
    int node = t >> 2;
    int q = t & 3;

    int s = __ldg(&g_start[node]);
    int e = (node + 1 < N_NODES) ? __ldg(&g_start[node + 1]) : N_EDGES;
    if (q == 0) g_cnt[node] = 0;                   // restore invariant

    float4 a0 = make_float4(0.f, 0.f, 0.f, 0.f);
    float4 a1 = make_float4(0.f, 0.f, 0.f, 0.f);

    int i = s;
    if (i < e) {
        int src = __ldg(&g_csr_src[i]);            // prologue index
        for (; i + 1 < e; i += 2) {
            int src_n1 = __ldg(&g_csr_src[i + 1]); // prefetch i+1
            float4 v0 = g_y[src * 4 + q];
            int src_n2 = (i + 2 < e) ? __ldg(&g_csr_src[i + 2]) : 0;
            float4 v1 = g_y[src_n1 * 4 + q];
            a0.x += v0.x; a0.y += v0.y; a0.z += v0.z; a0.w += v0.w;
            a1.x += v1.x; a1.y += v1.y; a1.z += v1.z; a1.w += v1.w;
            src = src_n2;
        }
        if (i < e) {                               // odd tail
            float4 v = g_y[src * 4 + q];
            a0.x += v.x; a0.y += v.y; a0.z += v.z; a0.w += v.w;
        }
    }

    float4 a;
    a.x = a0.x + a1.x; a.y = a0.y + a1.y;
    a.z = a0.z + a1.z; a.w = a0.w + a1.w;

    float inv = __fdividef(1.0f, fmaxf((float)(e - s), 1.0f));
    float4 z = g_z[node * 4 + q];
    float4 o;
    o.x = fmaxf(fmaf(a.x, inv, z.x), 0.0f);
    o.y = fmaxf(fmaf(a.y, inv, z.y), 0.0f);
    o.z = fmaxf(fmaf(a.z, inv, z.z), 0.0f);
    o.w = fmaxf(fmaf(a.w, inv, z.w), 0.0f);
    ((float4*)out)[t] = o;
}

extern "C" void kernel_launch(void* const* d_in, const int* in_sizes, int n_in,
                              void* d_out, int out_size) {
    const float* x  = (const float*)d_in[0];
    const void*  ei = d_in[1];
    const float* Wl = (const float*)d_in[2];
    const float* bl = (const float*)d_in[3];
    const float* Wr = (const float*)d_in[4];
    float* out = (float*)d_out;

    proj_kernel<<<NB_NODES, 256>>>(x, Wl, bl, Wr, ei);
    scan_kernel<<<NB_NODES, 256>>>();
    scatter_kernel<<<(N_EDGES / 2 + 255) / 256, 256>>>(ei);
    gather_fin_kernel<<<(N_NODES * 4 + 255) / 256, 256>>>(out);
}